// round 1
// baseline (speedup 1.0000x reference)
#include <cuda_runtime.h>

// EarthMoverDistance: approx auction match + cost, B=8, N=M=2048.
// Strategy: never materialize d2 or match. Per level, 3 compute-bound sweeps:
//   A (by row):  rowsum_n = sum_m exp(c*d2)*remainR[m]  -> rowscale
//   B (by col):  sumB_m  = sum_n exp(c*d2)*rowscale[n]  -> colscale, rcR, remainR update
//   C (by row):  u = exp(c*d2)*rcR[m]; cost += rowscale*u*sqrt(d2); remainL update
// remainR update needs NO extra sweep: colsumW = colscale*(ss-1e-9).
// Warp-uniform ballot skips the EX2/accumulation when exp underflows for the
// whole warp-iteration (dominant at levels -16384..-64).

#define NB 8
#define NP 2048
#define SPLIT 8                 // lanes per row/column
#define ROWS_PER_BLOCK 32
#define BLOCK (SPLIT * ROWS_PER_BLOCK)   // 256 threads
#define FULL 0xFFFFFFFFu

// Scratch (static __device__ — no allocation in kernel_launch)
__device__ float4 g_P1[NB * NP];   // {x1,y1,z1, rowscale}
__device__ float4 g_P2A[NB * NP];  // {x2,y2,z2, remainR}
__device__ float4 g_P2C[NB * NP];  // {x2,y2,z2, rcR = remainR*colscale}
__device__ float  g_remainL[NB * NP];
__device__ float  g_cost[NB];

__global__ void emd_init(const float* __restrict__ x1,
                         const float* __restrict__ x2, int total) {
    int i = blockIdx.x * blockDim.x + threadIdx.x;
    if (i < NB) g_cost[i] = 0.0f;
    if (i < total) {
        g_P1[i]  = make_float4(x1[3*i], x1[3*i+1], x1[3*i+2], 0.0f);
        g_P2A[i] = make_float4(x2[3*i], x2[3*i+1], x2[3*i+2], 1.0f); // multiR = 1
        g_remainL[i] = 1.0f;                                         // multiL = 1
    }
}

// ---- Pass A: row sums -> rowscale ----
__global__ __launch_bounds__(BLOCK) void emd_passA(float c) {
    int sub = threadIdx.x & (SPLIT - 1);
    int row = threadIdx.x >> 3;                   // 0..31
    int b   = blockIdx.x / (NP / ROWS_PER_BLOCK);
    int n   = (blockIdx.x % (NP / ROWS_PER_BLOCK)) * ROWS_PER_BLOCK + row;
    int idx = b * NP + n;

    float4 p = g_P1[idx];
    const float4* __restrict__ q = g_P2A + b * NP;

    float sum = 0.0f;
    #pragma unroll 4
    for (int m = sub; m < NP; m += SPLIT) {
        float4 qq = __ldg(q + m);
        float dx = p.x - qq.x, dy = p.y - qq.y, dz = p.z - qq.z;
        float d2 = fmaf(dx, dx, fmaf(dy, dy, dz * dz));
        float t = c * d2;
        if (__any_sync(FULL, t > -125.0f))
            sum = fmaf(exp2f(t), qq.w, sum);      // qq.w = remainR[m]
    }
    sum += __shfl_xor_sync(FULL, sum, 1);
    sum += __shfl_xor_sync(FULL, sum, 2);
    sum += __shfl_xor_sync(FULL, sum, 4);

    if (sub == 0) {
        float rowscale = g_remainL[idx] / (sum + 1e-9f);
        g_P1[idx] = make_float4(p.x, p.y, p.z, rowscale);
    }
}

// ---- Pass B: column sums -> colscale, rcR, remainR update ----
__global__ __launch_bounds__(BLOCK) void emd_passB(float c) {
    int sub = threadIdx.x & (SPLIT - 1);
    int col = threadIdx.x >> 3;
    int b   = blockIdx.x / (NP / ROWS_PER_BLOCK);
    int m   = (blockIdx.x % (NP / ROWS_PER_BLOCK)) * ROWS_PER_BLOCK + col;
    int idx = b * NP + m;

    float4 p = g_P2A[idx];                        // p.w = remainR[m]
    const float4* __restrict__ q = g_P1 + b * NP;

    float sum = 0.0f;
    #pragma unroll 4
    for (int n = sub; n < NP; n += SPLIT) {
        float4 qq = __ldg(q + n);
        float dx = p.x - qq.x, dy = p.y - qq.y, dz = p.z - qq.z;
        float d2 = fmaf(dx, dx, fmaf(dy, dy, dz * dz));
        float t = c * d2;
        if (__any_sync(FULL, t > -125.0f))
            sum = fmaf(exp2f(t), qq.w, sum);      // qq.w = rowscale[n]
    }
    sum += __shfl_xor_sync(FULL, sum, 1);
    sum += __shfl_xor_sync(FULL, sum, 2);
    sum += __shfl_xor_sync(FULL, sum, 4);

    if (sub == 0) {
        float remainR = p.w;
        float ss = fmaf(remainR, sum, 1e-9f);     // ss = remainR*sumB + 1e-9
        float cs = fminf(remainR / ss, 1.0f);     // colscale
        float rcR = remainR * cs;
        float colW = cs * (remainR * sum);        // sum_n of final w for this column
        float newR = fmaxf(remainR - colW, 0.0f);
        g_P2C[idx] = make_float4(p.x, p.y, p.z, rcR);
        g_P2A[idx] = make_float4(p.x, p.y, p.z, newR);
    }
}

// ---- Pass C: cost accumulation + remainL update ----
__global__ __launch_bounds__(BLOCK) void emd_passC(float c) {
    __shared__ float sc[ROWS_PER_BLOCK];
    int sub = threadIdx.x & (SPLIT - 1);
    int row = threadIdx.x >> 3;
    int b   = blockIdx.x / (NP / ROWS_PER_BLOCK);
    int n   = (blockIdx.x % (NP / ROWS_PER_BLOCK)) * ROWS_PER_BLOCK + row;
    int idx = b * NP + n;

    float4 p = g_P1[idx];                         // p.w = rowscale[n]
    const float4* __restrict__ q = g_P2C + b * NP;

    float usum = 0.0f, csum = 0.0f;
    #pragma unroll 4
    for (int m = sub; m < NP; m += SPLIT) {
        float4 qq = __ldg(q + m);
        float dx = p.x - qq.x, dy = p.y - qq.y, dz = p.z - qq.z;
        float d2 = fmaf(dx, dx, fmaf(dy, dy, dz * dz));
        float t = c * d2;
        if (__any_sync(FULL, t > -125.0f)) {
            float u = exp2f(t) * qq.w;            // qq.w = rcR[m]
            float sd = d2 * __frsqrt_rn(fmaxf(d2, 1e-30f)); // sqrt(d2), 0-safe
            usum += u;
            csum = fmaf(u, sd, csum);
        }
    }
    usum += __shfl_xor_sync(FULL, usum, 1);
    usum += __shfl_xor_sync(FULL, usum, 2);
    usum += __shfl_xor_sync(FULL, usum, 4);
    csum += __shfl_xor_sync(FULL, csum, 1);
    csum += __shfl_xor_sync(FULL, csum, 2);
    csum += __shfl_xor_sync(FULL, csum, 4);

    if (sub == 0) {
        float rsc = p.w;
        g_remainL[idx] = fmaxf(g_remainL[idx] - rsc * usum, 0.0f);
        sc[row] = rsc * csum;
    }
    __syncthreads();
    if (threadIdx.x < ROWS_PER_BLOCK) {
        float v = sc[threadIdx.x];
        v += __shfl_xor_sync(FULL, v, 1);
        v += __shfl_xor_sync(FULL, v, 2);
        v += __shfl_xor_sync(FULL, v, 4);
        v += __shfl_xor_sync(FULL, v, 8);
        v += __shfl_xor_sync(FULL, v, 16);
        if (threadIdx.x == 0) atomicAdd(&g_cost[b], v);
    }
}

__global__ void emd_final(float* __restrict__ out) {
    int i = threadIdx.x;
    if (i < NB) out[i] = g_cost[i];
}

extern "C" void kernel_launch(void* const* d_in, const int* in_sizes, int n_in,
                              void* d_out, int out_size) {
    const float* x1 = (const float*)d_in[0];
    const float* x2 = (const float*)d_in[1];
    float* out = (float*)d_out;

    const int total = NB * NP;
    emd_init<<<(total + 255) / 256, 256>>>(x1, x2, total);

    // levels: j = 7..0 -> -4^j ; j = -1 -> -0.25 ; j = -2 -> 0
    const float levels[10] = {-16384.f, -4096.f, -1024.f, -256.f, -64.f,
                              -16.f, -4.f, -1.f, -0.25f, 0.f};
    const float LOG2E = 1.4426950408889634f;
    const int grid = NB * (NP / ROWS_PER_BLOCK);  // 512 blocks

    for (int i = 0; i < 10; i++) {
        float c = levels[i] * LOG2E;              // exp(level*d2) = exp2(c*d2)
        emd_passA<<<grid, BLOCK>>>(c);
        emd_passB<<<grid, BLOCK>>>(c);
        emd_passC<<<grid, BLOCK>>>(c);
    }
    emd_final<<<1, 32>>>(out);
}

// round 3
// speedup vs baseline: 2.6860x; 2.6860x over previous
#include <cuda_runtime.h>

// EarthMoverDistance auction (B=8, N=M=2048), fused-pass version.
// Per level: B (column sweep) + CA (fused cost/remainL of level i with
// row-normalization of level i+1). d2 always recomputed (inputs are 96KB,
// L1-resident); nothing N*M is ever materialized.

#define NB 8
#define NP 2048
#define SPLIT 16                // lanes per row/column
#define RPB   16                // rows per block
#define BLOCK (SPLIT * RPB)     // 256 threads
#define GRID  (NB * (NP / RPB)) // 1024 blocks
#define FULL  0xFFFFFFFFu
#define SKIP_T (-125.0f)

// Scratch (static __device__ — no allocations)
__device__ float4 g_P1[NB * NP];     // {x1,y1,z1, rowscale}
__device__ float4 g_Q [NB * NP];     // {x2,y2,z2, rcR = remainR*colscale}
__device__ float  g_remainR[NB * NP];
__device__ float  g_remainL[NB * NP];
__device__ float  g_cost[NB];

__device__ __forceinline__ float ex2a(float x) {
    float r; asm("ex2.approx.f32 %0, %1;" : "=f"(r) : "f"(x)); return r;
}
__device__ __forceinline__ float sqrta(float x) {
    float r; asm("sqrt.approx.f32 %0, %1;" : "=f"(r) : "f"(x)); return r;
}
__device__ __forceinline__ float d2f(float4 p, float4 q) {
    float dx = p.x - q.x, dy = p.y - q.y, dz = p.z - q.z;
    return fmaf(dx, dx, fmaf(dy, dy, dz * dz));
}

__global__ void emd_init(const float* __restrict__ x1,
                         const float* __restrict__ x2, int total) {
    int i = blockIdx.x * blockDim.x + threadIdx.x;
    if (i < NB) g_cost[i] = 0.0f;
    if (i < total) {
        g_P1[i] = make_float4(x1[3*i], x1[3*i+1], x1[3*i+2], 0.0f);
        g_Q [i] = make_float4(x2[3*i], x2[3*i+1], x2[3*i+2], 0.0f);
        g_remainR[i] = 1.0f;   // multiR = 1 (N == M)
        g_remainL[i] = 1.0f;   // multiL = 1
    }
}

// ---- Pass A (level 0 only): rowsum over exp(c*d2)*remainR -> rowscale ----
__global__ __launch_bounds__(BLOCK) void emd_passA(float c) {
    int sub = threadIdx.x & (SPLIT - 1);
    int row = threadIdx.x >> 4;
    int b   = blockIdx.x / (NP / RPB);
    int n   = (blockIdx.x % (NP / RPB)) * RPB + row;
    int idx = b * NP + n;

    float4 p = g_P1[idx];
    const float4* __restrict__ q = g_Q + b * NP;
    const float*  __restrict__ rR = g_remainR + b * NP;

    float sum = 0.0f;
    for (int m0 = 0; m0 < NP; m0 += 4 * SPLIT) {
        int m = m0 + sub;
        float4 qa = __ldg(q + m);
        float4 qb = __ldg(q + m + SPLIT);
        float4 qc = __ldg(q + m + 2*SPLIT);
        float4 qd = __ldg(q + m + 3*SPLIT);
        float ta = c * d2f(p, qa), tb = c * d2f(p, qb);
        float tc = c * d2f(p, qc), td = c * d2f(p, qd);
        float tmax = fmaxf(fmaxf(ta, tb), fmaxf(tc, td));
        if (__any_sync(FULL, tmax > SKIP_T)) {
            sum = fmaf(ex2a(ta), __ldg(rR + m),           sum);
            sum = fmaf(ex2a(tb), __ldg(rR + m + SPLIT),   sum);
            sum = fmaf(ex2a(tc), __ldg(rR + m + 2*SPLIT), sum);
            sum = fmaf(ex2a(td), __ldg(rR + m + 3*SPLIT), sum);
        }
    }
    sum += __shfl_xor_sync(FULL, sum, 1);
    sum += __shfl_xor_sync(FULL, sum, 2);
    sum += __shfl_xor_sync(FULL, sum, 4);
    sum += __shfl_xor_sync(FULL, sum, 8);

    if (sub == 0) {
        float rowscale = g_remainL[idx] / (sum + 1e-9f);
        g_P1[idx] = make_float4(p.x, p.y, p.z, rowscale);
    }
}

// ---- Pass B: column sums -> colscale; writes rcR (in g_Q.w) + remainR ----
__global__ __launch_bounds__(BLOCK) void emd_passB(float c) {
    int sub = threadIdx.x & (SPLIT - 1);
    int col = threadIdx.x >> 4;
    int b   = blockIdx.x / (NP / RPB);
    int m   = (blockIdx.x % (NP / RPB)) * RPB + col;
    int idx = b * NP + m;

    float4 p = g_Q[idx];
    const float4* __restrict__ q = g_P1 + b * NP;   // q.w = rowscale[n]

    float sum = 0.0f;
    for (int n0 = 0; n0 < NP; n0 += 4 * SPLIT) {
        int n = n0 + sub;
        float4 qa = __ldg(q + n);
        float4 qb = __ldg(q + n + SPLIT);
        float4 qc = __ldg(q + n + 2*SPLIT);
        float4 qd = __ldg(q + n + 3*SPLIT);
        float ta = c * d2f(p, qa), tb = c * d2f(p, qb);
        float tc = c * d2f(p, qc), td = c * d2f(p, qd);
        float tmax = fmaxf(fmaxf(ta, tb), fmaxf(tc, td));
        if (__any_sync(FULL, tmax > SKIP_T)) {
            sum = fmaf(ex2a(ta), qa.w, sum);
            sum = fmaf(ex2a(tb), qb.w, sum);
            sum = fmaf(ex2a(tc), qc.w, sum);
            sum = fmaf(ex2a(td), qd.w, sum);
        }
    }
    sum += __shfl_xor_sync(FULL, sum, 1);
    sum += __shfl_xor_sync(FULL, sum, 2);
    sum += __shfl_xor_sync(FULL, sum, 4);
    sum += __shfl_xor_sync(FULL, sum, 8);

    if (sub == 0) {
        float remainR = g_remainR[idx];
        float ss  = fmaf(remainR, sum, 1e-9f);      // ss = colsum + 1e-9
        float cs  = fminf(remainR / ss, 1.0f);      // colscale
        float rcR = remainR * cs;
        float colW = cs * (remainR * sum);          // final column mass
        g_Q[idx] = make_float4(p.x, p.y, p.z, rcR);
        g_remainR[idx] = fmaxf(remainR - colW, 0.0f);
    }
}

// ---- Fused pass CA: cost + remainL of level i (c1), rowscale of level i+1 (c2)
__global__ __launch_bounds__(BLOCK) void emd_passCA(float c1, float c2) {
    __shared__ float sc[RPB];
    int sub = threadIdx.x & (SPLIT - 1);
    int row = threadIdx.x >> 4;
    int b   = blockIdx.x / (NP / RPB);
    int n   = (blockIdx.x % (NP / RPB)) * RPB + row;
    int idx = b * NP + n;

    float4 p = g_P1[idx];                           // p.w = rowscale[n]
    const float4* __restrict__ q  = g_Q + b * NP;   // q.w = rcR[m]
    const float*  __restrict__ rR = g_remainR + b * NP;

    float usum = 0.0f, csum = 0.0f, sum2 = 0.0f;
    for (int m0 = 0; m0 < NP; m0 += 4 * SPLIT) {
        int m = m0 + sub;
        float4 qa = __ldg(q + m);
        float4 qb = __ldg(q + m + SPLIT);
        float4 qc = __ldg(q + m + 2*SPLIT);
        float4 qd = __ldg(q + m + 3*SPLIT);
        float da = d2f(p, qa), db = d2f(p, qb);
        float dc = d2f(p, qc), dd = d2f(p, qd);
        float dmax = fmaxf(fmaxf(da, db), fmaxf(dc, dd));
        float dmin = fminf(fminf(da, db), fminf(dc, dd));
        // level i (strong): active iff c1*dmin > SKIP_T  (c1 <= 0)
        if (__any_sync(FULL, c1 * dmin > SKIP_T)) {
            float ua = ex2a(c1 * da) * qa.w;
            float ub = ex2a(c1 * db) * qb.w;
            float uc = ex2a(c1 * dc) * qc.w;
            float ud = ex2a(c1 * dd) * qd.w;
            usum += (ua + ub) + (uc + ud);
            csum = fmaf(ua, sqrta(da), csum);
            csum = fmaf(ub, sqrta(db), csum);
            csum = fmaf(uc, sqrta(dc), csum);
            csum = fmaf(ud, sqrta(dd), csum);
        }
        // level i+1 (weaker): |c2| <= |c1|
        if (__any_sync(FULL, c2 * dmin > SKIP_T)) {
            sum2 = fmaf(ex2a(c2 * da), __ldg(rR + m),           sum2);
            sum2 = fmaf(ex2a(c2 * db), __ldg(rR + m + SPLIT),   sum2);
            sum2 = fmaf(ex2a(c2 * dc), __ldg(rR + m + 2*SPLIT), sum2);
            sum2 = fmaf(ex2a(c2 * dd), __ldg(rR + m + 3*SPLIT), sum2);
        }
        (void)dmax;
    }
    usum += __shfl_xor_sync(FULL, usum, 1);
    usum += __shfl_xor_sync(FULL, usum, 2);
    usum += __shfl_xor_sync(FULL, usum, 4);
    usum += __shfl_xor_sync(FULL, usum, 8);
    csum += __shfl_xor_sync(FULL, csum, 1);
    csum += __shfl_xor_sync(FULL, csum, 2);
    csum += __shfl_xor_sync(FULL, csum, 4);
    csum += __shfl_xor_sync(FULL, csum, 8);
    sum2 += __shfl_xor_sync(FULL, sum2, 1);
    sum2 += __shfl_xor_sync(FULL, sum2, 2);
    sum2 += __shfl_xor_sync(FULL, sum2, 4);
    sum2 += __shfl_xor_sync(FULL, sum2, 8);

    if (sub == 0) {
        float rsc = p.w;
        float newL = fmaxf(g_remainL[idx] - rsc * usum, 0.0f);
        g_remainL[idx] = newL;
        // rowscale for next level (unused garbage on last level, harmless)
        g_P1[idx] = make_float4(p.x, p.y, p.z, newL / (sum2 + 1e-9f));
        sc[row] = rsc * csum;
    }
    __syncthreads();
    if (threadIdx.x < RPB) {
        float v = sc[threadIdx.x];
        v += __shfl_xor_sync(0xFFFFu, v, 1);
        v += __shfl_xor_sync(0xFFFFu, v, 2);
        v += __shfl_xor_sync(0xFFFFu, v, 4);
        v += __shfl_xor_sync(0xFFFFu, v, 8);
        if (threadIdx.x == 0) atomicAdd(&g_cost[b], v);
    }
}

__global__ void emd_final(float* __restrict__ out) {
    int i = threadIdx.x;
    if (i < NB) out[i] = g_cost[i];
}

extern "C" void kernel_launch(void* const* d_in, const int* in_sizes, int n_in,
                              void* d_out, int out_size) {
    const float* x1 = (const float*)d_in[0];
    const float* x2 = (const float*)d_in[1];
    float* out = (float*)d_out;

    const int total = NB * NP;
    emd_init<<<(total + 255) / 256, 256>>>(x1, x2, total);

    // levels j = 7..0 -> -4^j ; j=-1 -> -0.25 ; j=-2 -> 0
    const float levels[10] = {-16384.f, -4096.f, -1024.f, -256.f, -64.f,
                              -16.f, -4.f, -1.f, -0.25f, 0.f};
    const float LOG2E = 1.4426950408889634f;

    emd_passA<<<GRID, BLOCK>>>(levels[0] * LOG2E);
    for (int i = 0; i < 10; i++) {
        float c1 = levels[i] * LOG2E;
        float c2 = (i + 1 < 10) ? levels[i + 1] * LOG2E : 0.0f;
        emd_passB <<<GRID, BLOCK>>>(c1);
        emd_passCA<<<GRID, BLOCK>>>(c1, c2);
    }
    emd_final<<<1, 32>>>(out);
}